// round 8
// baseline (speedup 1.0000x reference)
#include <cuda_runtime.h>

// PrimitiveGate: apply complex 2x2 gate to qubit axis 12 of a 23-qubit state,
// batch 4. State layout: (DIM, BATCH) float32, re and im planes separate.
// Output: (2, DIM, BATCH) float32 -> [out_re | out_im].
//
// Axis 12 of 23 -> bit 10 of dim index. BATCH=4 floats -> one float4/row.
//
// R8: persistent grid-stride single-wave launch (148 SMs x 8 CTAs x 256thr),
// ~14 pairs per thread. Eliminates 12.8 wave transitions (T_wave_trans~2360cyc
// each) of the 13.8-wave launch; identical per-access coalescing/caching.
// Session evidence: traffic (536 MB) irreducible, coalescing exact, .cs
// neutral, ILP-for-occupancy regressive, block shape neutral. DRAM busy 81.5%
// — this probes whether wave-boundary ramps are part of the remaining 18%.

#define N_QUBITS 23
#define TARGET_BIT 10            // N_QUBITS - 1 - TARGET_Q(12)
#define DIM (1u << N_QUBITS)     // 8388608
#define NPAIRS (DIM >> 1)        // 4194304
#define LOWMASK ((1u << TARGET_BIT) - 1u)

#define NBLOCKS 1184             // 148 SMs * 8 resident CTAs (32 regs, 256 thr)
#define TPB 256
#define STRIDE (NBLOCKS * TPB)   // 303104 threads, single wave

__global__ void __launch_bounds__(TPB)
gate_kernel(const float4* __restrict__ sre,
            const float4* __restrict__ sim,
            const float*  __restrict__ mre,
            const float*  __restrict__ mim,
            float4* __restrict__ out)
{
    // 2x2 complex gate, row-major (tiny, L1-hot)
    float m00r = __ldg(&mre[0]), m01r = __ldg(&mre[1]);
    float m10r = __ldg(&mre[2]), m11r = __ldg(&mre[3]);
    float m00i = __ldg(&mim[0]), m01i = __ldg(&mim[1]);
    float m10i = __ldg(&mim[2]), m11i = __ldg(&mim[3]);

    for (unsigned p = blockIdx.x * (unsigned)TPB + threadIdx.x;
         p < NPAIRS; p += (unsigned)STRIDE)
    {
        // i0: insert a 0 at bit TARGET_BIT; i1 = i0 | (1<<TARGET_BIT)
        unsigned i0 = ((p & ~LOWMASK) << 1) | (p & LOWMASK);
        unsigned i1 = i0 | (1u << TARGET_BIT);

        // Front-batched independent streaming loads (MLP = 4), evict-first
        float4 a_re = __ldcs(&sre[i0]);
        float4 b_re = __ldcs(&sre[i1]);
        float4 a_im = __ldcs(&sim[i0]);
        float4 b_im = __ldcs(&sim[i1]);

        float4 o0r, o0i, o1r, o1i;

#define LANE(f)                                                                 \
    do {                                                                        \
        float s0r = a_re.f, s0i = a_im.f, s1r = b_re.f, s1i = b_im.f;           \
        o0r.f = fmaf(m00r, s0r, fmaf(-m00i, s0i, fmaf(m01r, s1r, -m01i * s1i)));\
        o0i.f = fmaf(m00r, s0i, fmaf( m00i, s0r, fmaf(m01r, s1i,  m01i * s1r)));\
        o1r.f = fmaf(m10r, s0r, fmaf(-m10i, s0i, fmaf(m11r, s1r, -m11i * s1i)));\
        o1i.f = fmaf(m10r, s0i, fmaf( m10i, s0r, fmaf(m11r, s1i,  m11i * s1r)));\
    } while (0)

        LANE(x); LANE(y); LANE(z); LANE(w);
#undef LANE

        // out_re plane at [0, DIM), out_im plane at [DIM, 2*DIM) (float4 units)
        __stcs(&out[i0],       o0r);
        __stcs(&out[i1],       o1r);
        __stcs(&out[DIM + i0], o0i);
        __stcs(&out[DIM + i1], o1i);
    }
}

extern "C" void kernel_launch(void* const* d_in, const int* in_sizes, int n_in,
                              void* d_out, int out_size)
{
    const float4* sre = (const float4*)d_in[0];
    const float4* sim = (const float4*)d_in[1];
    const float*  mre = (const float*)d_in[2];
    const float*  mim = (const float*)d_in[3];
    float4* out = (float4*)d_out;

    gate_kernel<<<NBLOCKS, TPB>>>(sre, sim, mre, mim, out);
}

// round 9
// speedup vs baseline: 1.1284x; 1.1284x over previous
#include <cuda_runtime.h>

// PrimitiveGate: apply complex 2x2 gate to qubit axis 12 of a 23-qubit state,
// batch 4. State layout: (DIM, BATCH) float32, re and im planes separate.
// Output: (2, DIM, BATCH) float32 -> [out_re | out_im].
//
// Axis 12 of 23 (axis 0 = MSB) -> bit 10 of the dim index.
// BATCH=4 contiguous floats per dim index -> one float4 per (dim, batch-row).
//
// FINAL — HBM-roofline kernel. 536 MB irreducible traffic at ~6.5 TB/s
// (~82% of 8 TB/s spec = the B300 mixed-R/W streaming ceiling). Full session
// lever matrix (all bracketing perturbations tested):
//   R2: .cs streaming hints      -> neutral   (L2 policy not the limiter)
//   R3: ILP=2 / MLP=8 per thread -> regressed (occ 80->63%, DRAM -2.6%)
//   R4/R6/R7: re-bench           -> reproduced (noise +-1%)
//   R5: block 256->512           -> neutral   (scheduling not the limiter)
//   R8: persistent grid-stride   -> regressed (DRAM -6%: loop-carried deps
//       behind stores throttle per-warp MLP; short dependency-free CTAs are
//       the optimal DRAM-queue feeder)
// One pair per thread, 32 regs, ~80% occ, exact float4 coalescing,
// 100% sector efficiency. The residual ~18% to spec is DRAM controller
// R/W bus-turnaround + refresh — not SM-addressable.

#define N_QUBITS 23
#define TARGET_BIT 10            // N_QUBITS - 1 - TARGET_Q(12)
#define DIM (1u << N_QUBITS)     // 8388608
#define NPAIRS (DIM >> 1)        // 4194304
#define LOWMASK ((1u << TARGET_BIT) - 1u)

__global__ void __launch_bounds__(256)
gate_kernel(const float4* __restrict__ sre,
            const float4* __restrict__ sim,
            const float*  __restrict__ mre,
            const float*  __restrict__ mim,
            float4* __restrict__ out)
{
    unsigned p = blockIdx.x * 256u + threadIdx.x;

    // i0: insert a 0 at bit TARGET_BIT; i1 = i0 | (1<<TARGET_BIT)
    unsigned i0 = ((p & ~LOWMASK) << 1) | (p & LOWMASK);
    unsigned i1 = i0 | (1u << TARGET_BIT);

    // Front-batched independent streaming loads (MLP = 4), evict-first
    float4 a_re = __ldcs(&sre[i0]);
    float4 b_re = __ldcs(&sre[i1]);
    float4 a_im = __ldcs(&sim[i0]);
    float4 b_im = __ldcs(&sim[i1]);

    // 2x2 complex gate, row-major (tiny, hot in L1 — normal loads)
    float m00r = __ldg(&mre[0]), m01r = __ldg(&mre[1]);
    float m10r = __ldg(&mre[2]), m11r = __ldg(&mre[3]);
    float m00i = __ldg(&mim[0]), m01i = __ldg(&mim[1]);
    float m10i = __ldg(&mim[2]), m11i = __ldg(&mim[3]);

    float4 o0r, o0i, o1r, o1i;

#define LANE(f)                                                                 \
    do {                                                                        \
        float s0r = a_re.f, s0i = a_im.f, s1r = b_re.f, s1i = b_im.f;           \
        o0r.f = fmaf(m00r, s0r, fmaf(-m00i, s0i, fmaf(m01r, s1r, -m01i * s1i)));\
        o0i.f = fmaf(m00r, s0i, fmaf( m00i, s0r, fmaf(m01r, s1i,  m01i * s1r)));\
        o1r.f = fmaf(m10r, s0r, fmaf(-m10i, s0i, fmaf(m11r, s1r, -m11i * s1i)));\
        o1i.f = fmaf(m10r, s0i, fmaf( m10i, s0r, fmaf(m11r, s1i,  m11i * s1r)));\
    } while (0)

    LANE(x); LANE(y); LANE(z); LANE(w);
#undef LANE

    // out_re plane at [0, DIM), out_im plane at [DIM, 2*DIM) (in float4 units)
    // Streaming stores: full-line coalesced, evict-first.
    __stcs(&out[i0],       o0r);
    __stcs(&out[i1],       o1r);
    __stcs(&out[DIM + i0], o0i);
    __stcs(&out[DIM + i1], o1i);
}

extern "C" void kernel_launch(void* const* d_in, const int* in_sizes, int n_in,
                              void* d_out, int out_size)
{
    const float4* sre = (const float4*)d_in[0];
    const float4* sim = (const float4*)d_in[1];
    const float*  mre = (const float*)d_in[2];
    const float*  mim = (const float*)d_in[3];
    float4* out = (float4*)d_out;

    dim3 grid(NPAIRS / 256);  // 16384 blocks, exact
    gate_kernel<<<grid, 256>>>(sre, sim, mre, mim, out);
}

// round 10
// speedup vs baseline: 1.1289x; 1.0004x over previous
#include <cuda_runtime.h>

// PrimitiveGate: apply complex 2x2 gate to qubit axis 12 of a 23-qubit state,
// batch 4. State layout: (DIM, BATCH) float32, re and im planes separate.
// Output: (2, DIM, BATCH) float32 -> [out_re | out_im].
//
// Axis 12 of 23 (axis 0 = MSB) -> bit 10 of the dim index.
// BATCH=4 contiguous floats per dim index -> one float4 per (dim, batch-row).
//
// HBM-roofline kernel: 536 MB irreducible traffic at ~6.5 TB/s (~82% of
// spec, the B300 mixed-R/W streaming ceiling). Lever matrix:
//   R2 .cs hints: neutral | R3 ILP=2: regressed | R5 TPB512: neutral
//   R8 persistent grid-stride: regressed -6% (loop-carried deps throttle MLP;
//      short dependency-free CTAs feed the DRAM queue best)
// R10: extrapolate R8's lesson -> TPB=128 (32768 CTAs, even shorter-lived,
// same occupancy & identical per-instruction memory pattern). Expected
// neutral-to-marginal; final probe.

#define N_QUBITS 23
#define TARGET_BIT 10            // N_QUBITS - 1 - TARGET_Q(12)
#define DIM (1u << N_QUBITS)     // 8388608
#define NPAIRS (DIM >> 1)        // 4194304
#define LOWMASK ((1u << TARGET_BIT) - 1u)
#define TPB 128

__global__ void __launch_bounds__(TPB)
gate_kernel(const float4* __restrict__ sre,
            const float4* __restrict__ sim,
            const float*  __restrict__ mre,
            const float*  __restrict__ mim,
            float4* __restrict__ out)
{
    unsigned p = blockIdx.x * (unsigned)TPB + threadIdx.x;

    // i0: insert a 0 at bit TARGET_BIT; i1 = i0 | (1<<TARGET_BIT)
    unsigned i0 = ((p & ~LOWMASK) << 1) | (p & LOWMASK);
    unsigned i1 = i0 | (1u << TARGET_BIT);

    // Front-batched independent streaming loads (MLP = 4), evict-first
    float4 a_re = __ldcs(&sre[i0]);
    float4 b_re = __ldcs(&sre[i1]);
    float4 a_im = __ldcs(&sim[i0]);
    float4 b_im = __ldcs(&sim[i1]);

    // 2x2 complex gate, row-major (tiny, hot in L1 — normal loads)
    float m00r = __ldg(&mre[0]), m01r = __ldg(&mre[1]);
    float m10r = __ldg(&mre[2]), m11r = __ldg(&mre[3]);
    float m00i = __ldg(&mim[0]), m01i = __ldg(&mim[1]);
    float m10i = __ldg(&mim[2]), m11i = __ldg(&mim[3]);

    float4 o0r, o0i, o1r, o1i;

#define LANE(f)                                                                 \
    do {                                                                        \
        float s0r = a_re.f, s0i = a_im.f, s1r = b_re.f, s1i = b_im.f;           \
        o0r.f = fmaf(m00r, s0r, fmaf(-m00i, s0i, fmaf(m01r, s1r, -m01i * s1i)));\
        o0i.f = fmaf(m00r, s0i, fmaf( m00i, s0r, fmaf(m01r, s1i,  m01i * s1r)));\
        o1r.f = fmaf(m10r, s0r, fmaf(-m10i, s0i, fmaf(m11r, s1r, -m11i * s1i)));\
        o1i.f = fmaf(m10r, s0i, fmaf( m10i, s0r, fmaf(m11r, s1i,  m11i * s1r)));\
    } while (0)

    LANE(x); LANE(y); LANE(z); LANE(w);
#undef LANE

    // out_re plane at [0, DIM), out_im plane at [DIM, 2*DIM) (in float4 units)
    // Streaming stores: full-line coalesced, evict-first.
    __stcs(&out[i0],       o0r);
    __stcs(&out[i1],       o1r);
    __stcs(&out[DIM + i0], o0i);
    __stcs(&out[DIM + i1], o1i);
}

extern "C" void kernel_launch(void* const* d_in, const int* in_sizes, int n_in,
                              void* d_out, int out_size)
{
    const float4* sre = (const float4*)d_in[0];
    const float4* sim = (const float4*)d_in[1];
    const float*  mre = (const float*)d_in[2];
    const float*  mim = (const float*)d_in[3];
    float4* out = (float4*)d_out;

    dim3 grid(NPAIRS / TPB);  // 32768 blocks, exact
    gate_kernel<<<grid, TPB>>>(sre, sim, mre, mim, out);
}